// round 4
// baseline (speedup 1.0000x reference)
#include <cuda_runtime.h>
#include <cstdint>

// FWHT over rows of length 4096: H4096 = H2^{⊗12}.
// One row per CTA, 512 threads, 8 elements/thread.
// 4 register-resident H8 rounds (3 bits each) + 3 smem exchanges:
//   round 1: bits {0,1,11}   (from the coalesced float4 load layout)
//   round 2: bits {2,3,4}
//   round 3: bits {5,6,7}
//   round 4: bits {8,9,10}
// XOR swizzle (bits 5..7 -> bits 2..4) keeps every pattern 32-bank
// conflict-free. __launch_bounds__(512,4) -> <=32 regs -> ~100% occupancy.

#define FWHT_N 4096
#define FWHT_THREADS 512

__device__ __forceinline__ int fwht_swz(int i) {
    return i ^ (((i >> 5) & 7) << 2);
}

__device__ __forceinline__ void fwht_h8(float* v) {
#pragma unroll
    for (int h = 1; h < 8; h <<= 1) {
#pragma unroll
        for (int s = 0; s < 8; s += 2 * h) {
#pragma unroll
            for (int k = 0; k < h; k++) {
                float a = v[s + k];
                float b = v[s + k + h];
                v[s + k]     = a + b;
                v[s + k + h] = a - b;
            }
        }
    }
}

__global__ void __launch_bounds__(FWHT_THREADS, 4)
fwht4096_kernel(const float* __restrict__ x,
                const float* __restrict__ scale,
                float* __restrict__ out)
{
    __shared__ float S[FWHT_N];

    const int row = blockIdx.x;
    const int t   = threadIdx.x;

    const float4* xr = reinterpret_cast<const float4*>(x) + (size_t)row * (FWHT_N / 4);

    float v[8];

    // ---- load (coalesced float4): v[4j+k] = x[row, 2048*j + 4*t + k]
    // register index (j<<2)|k carries bits {0,1,11} of the element index.
#pragma unroll
    for (int j = 0; j < 2; j++) {
        float4 f = xr[512 * j + t];
        v[4 * j + 0] = f.x;
        v[4 * j + 1] = f.y;
        v[4 * j + 2] = f.z;
        v[4 * j + 3] = f.w;
    }

    // ---- round 1: butterflies over bits {0,1,11}
    fwht_h8(v);

    // swizzled float4 stores (bits 5..7 constant within each float4)
#pragma unroll
    for (int j = 0; j < 2; j++) {
        int p = fwht_swz(2048 * j + 4 * t);
        *reinterpret_cast<float4*>(&S[p]) =
            make_float4(v[4 * j + 0], v[4 * j + 1], v[4 * j + 2], v[4 * j + 3]);
    }
    __syncthreads();

    // ---- round 2: bits {2,3,4}; thread owns bits {0,1} and {5..11}
    {
        const int base = (t & 3) | ((t >> 2) << 5);
#pragma unroll
        for (int m = 0; m < 8; m++)
            v[m] = S[fwht_swz(base | (m << 2))];

        fwht_h8(v);

#pragma unroll
        for (int m = 0; m < 8; m++)
            S[fwht_swz(base | (m << 2))] = v[m];
    }
    __syncthreads();

    // ---- round 3: bits {5,6,7}; thread owns bits {0..4} and {8..11}
    {
        const int base = (t & 31) | ((t >> 5) << 8);
#pragma unroll
        for (int m = 0; m < 8; m++)
            v[m] = S[fwht_swz(base | (m << 5))];

        fwht_h8(v);

#pragma unroll
        for (int m = 0; m < 8; m++)
            S[fwht_swz(base | (m << 5))] = v[m];
    }
    __syncthreads();

    // ---- round 4: bits {8,9,10}; thread owns bits {0..7} and {11}
    {
        const int base = (t & 255) | ((t >> 8) << 11);
#pragma unroll
        for (int m = 0; m < 8; m++)
            v[m] = S[fwht_swz(base | (m << 8))];

        fwht_h8(v);

        const float sc = *scale;
        float* orow = out + (size_t)row * FWHT_N;
        // lanes cover 32 consecutive floats per m -> 128B coalesced stores
#pragma unroll
        for (int m = 0; m < 8; m++)
            orow[base | (m << 8)] = v[m] * sc;
    }
}

extern "C" void kernel_launch(void* const* d_in, const int* in_sizes, int n_in,
                              void* d_out, int out_size)
{
    const float* x     = (const float*)d_in[0];
    const float* scale = (const float*)d_in[1];
    float* out         = (float*)d_out;

    const int rows = in_sizes[0] / FWHT_N;

    fwht4096_kernel<<<rows, FWHT_THREADS>>>(x, scale, out);
}